// round 7
// baseline (speedup 1.0000x reference)
#include <cuda_runtime.h>
#include <cuda_fp16.h>

#define BB 32
#define LL 1024
#define HH 1280
#define PP 128
#define NROWS (BB * LL)
#define INVT 14.285714285714286f
#define C1F (14.285714285714286f * 1.4426950408889634f)

// ---------------------------------------------------------------------------
// Helpers
// ---------------------------------------------------------------------------
__device__ __forceinline__ unsigned smem_to_u32(const void* p) {
    unsigned a;
    asm("{ .reg .u64 t; cvta.to.shared.u64 t, %1; cvt.u32.u64 %0, t; }" : "=r"(a) : "l"(p));
    return a;
}
static __device__ __forceinline__ unsigned sw128(unsigned off) {
    return off ^ ((off >> 3) & 0x70);
}
__device__ __forceinline__ float ex2f(float x) {
    float r;
    asm("ex2.approx.f32 %0, %1;" : "=f"(r) : "f"(x));
    return r;
}
__device__ __forceinline__ unsigned f16pack(float lo, float hi) {
    unsigned r;
    asm("cvt.rn.f16x2.f32 %0, %1, %2;" : "=r"(r) : "f"(hi), "f"(lo));
    return r;
}

#define LDSM4(r0, r1, r2, r3, addr)                                          \
    asm volatile("ldmatrix.sync.aligned.m8n8.x4.shared.b16 {%0,%1,%2,%3}, [%4];" \
                 : "=r"(r0), "=r"(r1), "=r"(r2), "=r"(r3) : "r"(addr))

#define MMA(d, a, b)                                                         \
    asm volatile("mma.sync.aligned.m16n8k16.row.col.f32.f16.f16.f32 "        \
                 "{%0,%1,%2,%3},{%4,%5,%6,%7},{%8,%9},{%0,%1,%2,%3};"        \
                 : "+f"((d)[0]), "+f"((d)[1]), "+f"((d)[2]), "+f"((d)[3])    \
                 : "r"((a)[0]), "r"((a)[1]), "r"((a)[2]), "r"((a)[3]),       \
                   "r"((b)[0]), "r"((b)[1]))

#define CP16(dst, src) \
    asm volatile("cp.async.cg.shared.global [%0], [%1], 16;" :: "r"(dst), "l"(src))
#define CP_COMMIT() asm volatile("cp.async.commit_group;" ::: "memory")
#define CP_WAIT1()  asm volatile("cp.async.wait_group 1;" ::: "memory")
#define CP_WAIT0()  asm volatile("cp.async.wait_group 0;" ::: "memory")

// ---------------------------------------------------------------------------
// Device scratch
// ---------------------------------------------------------------------------
__device__ __align__(16) __half g_emb[NROWS * PP];
__device__ __align__(16) __half g_wt[PP * HH];   // [n][k] K-major
__device__ __align__(16) float g_P[BB * 4 * PP]; // per-batch label sums
__device__ float g_se[NROWS];
__device__ int g_cnt4[BB * 4];
__device__ int2 g_counts[BB];                    // (mask_sum, valid_sum)
__device__ float g_loss[BB];
__device__ int g_ok[BB];

// ---------------------------------------------------------------------------
// Kernel 0: W -> fp16, transposed to [n][k]
// ---------------------------------------------------------------------------
__global__ void kern_wt(const float* __restrict__ W) {
    int i = blockIdx.x * 256 + threadIdx.x;
    if (i >= HH * PP) return;
    int k = i / PP, n = i % PP;
    g_wt[n * HH + k] = __float2half_rn(W[i]);
}

// ---------------------------------------------------------------------------
// Kernel 1: proj + L2-normalize; invalid rows stored as zero
// ---------------------------------------------------------------------------
#define P_A  4096
#define P_B0 20480
#define PROJ_SMEM (20480 + 2 * 16384)

__global__ __launch_bounds__(256, 2)
void kern_proj(const float* __restrict__ hid, const float* __restrict__ bias,
               const int* __restrict__ amask, const int* __restrict__ labels) {
    extern __shared__ char sm[];
    const unsigned sb = smem_to_u32(sm);
    const int tid = threadIdx.x, lane = tid & 31, wid = tid >> 5;
    const int wm = wid & 3, wn = wid >> 2;
    const int m0 = wm * 32, n0 = wn * 64;
    const int row0 = blockIdx.x * 128;
    float* bias_s = (float*)sm;
    float* ssbuf = (float*)(sm + 512);

    if (tid < 128) bias_s[tid] = bias[tid];

    float acc[2][8][4];
#pragma unroll
    for (int mt = 0; mt < 2; mt++)
#pragma unroll
        for (int nt = 0; nt < 8; nt++)
#pragma unroll
            for (int e = 0; e < 4; e++) acc[mt][nt][e] = 0.f;

#pragma unroll
    for (int i = 0; i < 4; i++) {
        int u = i * 256 + tid;
        int n = u >> 3, k8 = u & 7;
        unsigned off = sw128((unsigned)(n * 128 + k8 * 16));
        CP16(sb + P_B0 + off, g_wt + (size_t)n * HH + k8 * 8);
    }
    CP_COMMIT();

    uint4 ra[4];
#pragma unroll
    for (int q = 0; q < 4; q++) {
        int u = q * 256 + tid;
        int row = u >> 3, k8 = u & 7;
        const float* s = hid + (size_t)(row0 + row) * HH + k8 * 8;
        float4 v0 = *(const float4*)s;
        float4 v1 = *(const float4*)(s + 4);
        ra[q] = make_uint4(f16pack(v0.x, v0.y), f16pack(v0.z, v0.w),
                           f16pack(v1.x, v1.y), f16pack(v1.z, v1.w));
    }

#pragma unroll 1
    for (int c = 0; c < 20; c++) {
        const int buf = c & 1;
        __syncthreads();
        if (c < 19) {
            const int k0n = (c + 1) * 64;
            const unsigned bdst = sb + P_B0 + (buf ^ 1) * 16384;
#pragma unroll
            for (int i = 0; i < 4; i++) {
                int u = i * 256 + tid;
                int n = u >> 3, k8 = u & 7;
                unsigned off = sw128((unsigned)(n * 128 + k8 * 16));
                CP16(bdst + off, g_wt + (size_t)n * HH + k0n + k8 * 8);
            }
            CP_COMMIT();
        }
#pragma unroll
        for (int q = 0; q < 4; q++) {
            int u = q * 256 + tid;
            int row = u >> 3, k8 = u & 7;
            unsigned off = sw128((unsigned)(row * 128 + k8 * 16));
            *(uint4*)(sm + P_A + off) = ra[q];
        }
        if (c < 19) {
            const int k0n = (c + 1) * 64;
#pragma unroll
            for (int q = 0; q < 4; q++) {
                int u = q * 256 + tid;
                int row = u >> 3, k8 = u & 7;
                const float* s = hid + (size_t)(row0 + row) * HH + k0n + k8 * 8;
                float4 v0 = *(const float4*)s;
                float4 v1 = *(const float4*)(s + 4);
                ra[q] = make_uint4(f16pack(v0.x, v0.y), f16pack(v0.z, v0.w),
                                   f16pack(v1.x, v1.y), f16pack(v1.z, v1.w));
            }
        }
        if (c < 19) CP_WAIT1(); else CP_WAIT0();
        __syncthreads();

        const unsigned b_base = sb + P_B0 + buf * 16384;
#pragma unroll
        for (int kk = 0; kk < 4; kk++) {
            unsigned ah[2][4], bh[8][2];
#pragma unroll
            for (int mt = 0; mt < 2; mt++) {
                unsigned r = m0 + mt * 16 + (lane & 15);
                unsigned off = sw128(r * 128 + kk * 32 + ((lane >> 4) << 4));
                LDSM4(ah[mt][0], ah[mt][1], ah[mt][2], ah[mt][3], sb + P_A + off);
            }
#pragma unroll
            for (int p = 0; p < 4; p++) {
                unsigned q = lane >> 3;
                unsigned nr = n0 + p * 16 + ((q >> 1) << 3) + (lane & 7);
                unsigned off = sw128(nr * 128 + kk * 32 + ((q & 1) << 4));
                unsigned t0, t1, t2, t3;
                LDSM4(t0, t1, t2, t3, b_base + off);
                bh[2 * p][0] = t0; bh[2 * p][1] = t1;
                bh[2 * p + 1][0] = t2; bh[2 * p + 1][1] = t3;
            }
#pragma unroll
            for (int mt = 0; mt < 2; mt++)
#pragma unroll
                for (int nt = 0; nt < 8; nt++)
                    MMA(acc[mt][nt], ah[mt], bh[nt]);
        }
    }

    // epilogue: bias, L2 norm, zero invalid rows, store fp16
    float ss[4] = {0.f, 0.f, 0.f, 0.f};
#pragma unroll
    for (int mt = 0; mt < 2; mt++)
#pragma unroll
        for (int nt = 0; nt < 8; nt++)
#pragma unroll
            for (int e = 0; e < 4; e++) {
                int s = e >> 1;
                int col = n0 + nt * 8 + (lane & 3) * 2 + (e & 1);
                float v = acc[mt][nt][e] + bias_s[col];
                acc[mt][nt][e] = v;
                ss[mt * 2 + s] += v * v;
            }
#pragma unroll
    for (int r2 = 0; r2 < 4; r2++) {
        ss[r2] += __shfl_xor_sync(0xffffffffu, ss[r2], 1);
        ss[r2] += __shfl_xor_sync(0xffffffffu, ss[r2], 2);
    }
    if ((lane & 3) == 0) {
#pragma unroll
        for (int r2 = 0; r2 < 4; r2++) {
            int rowg = wm * 32 + (r2 >> 1) * 16 + (lane >> 2) + (r2 & 1) * 8;
            ssbuf[wn * 128 + rowg] = ss[r2];
        }
    }
    __syncthreads();
#pragma unroll
    for (int r2 = 0; r2 < 4; r2++) {
        int mt = r2 >> 1, s = r2 & 1;
        int rowg = wm * 32 + mt * 16 + (lane >> 2) + s * 8;
        int gr = row0 + rowg;
        int vv = (amask[gr] != 0) && (labels[gr] != -100);
        float tot = ssbuf[rowg] + ssbuf[128 + rowg];
        float inv = rsqrtf(tot);
        inv = inv * (1.5f - 0.5f * tot * inv * inv);
        if (!vv) inv = 0.f;
        __half* oh = g_emb + (size_t)gr * PP;
#pragma unroll
        for (int nt = 0; nt < 8; nt++) {
            int col = n0 + nt * 8 + (lane & 3) * 2;
            *(unsigned*)(oh + col) =
                f16pack(acc[mt][nt][s * 2] * inv, acc[mt][nt][s * 2 + 1] * inv);
        }
    }
}

// ---------------------------------------------------------------------------
// Kernel PL: per-batch label sums P_l, label counts, mask/valid counts
// ---------------------------------------------------------------------------
__global__ __launch_bounds__(256)
void kern_pl(const int* __restrict__ amask, const int* __restrict__ labels) {
    __shared__ float Pp[4 * 4 * 128];   // [grp][l][d], 8 KB
    __shared__ int cbuf[8][6];
    const int b = blockIdx.x, tid = threadIdx.x, lane = tid & 31, w = tid >> 5;
    const int d2 = tid & 63, grp = tid >> 6;
    const __half* eb = g_emb + (size_t)b * LL * PP;

    float2 acc[4];
#pragma unroll
    for (int l = 0; l < 4; l++) acc[l] = make_float2(0.f, 0.f);
#pragma unroll 4
    for (int r = 0; r < 256; r++) {
        int row = grp * 256 + r;
        int lb = labels[b * LL + row];
        int vv = (amask[b * LL + row] != 0) && (lb != -100);
        float2 f = __half22float2(*(const __half2*)(eb + (size_t)row * PP + d2 * 2));
#pragma unroll
        for (int l = 0; l < 4; l++)
            if (vv && lb == l) { acc[l].x += f.x; acc[l].y += f.y; }
    }
#pragma unroll
    for (int l = 0; l < 4; l++) {
        Pp[grp * 512 + l * 128 + d2 * 2]     = acc[l].x;
        Pp[grp * 512 + l * 128 + d2 * 2 + 1] = acc[l].y;
    }
    int c[6] = {0, 0, 0, 0, 0, 0};
#pragma unroll
    for (int q = 0; q < 4; q++) {
        int row = tid * 4 + q;
        int mm = amask[b * LL + row], lb = labels[b * LL + row];
        int vv = (mm != 0) && (lb != -100);
        c[0] += (mm != 0); c[1] += vv;
#pragma unroll
        for (int l = 0; l < 4; l++) c[2 + l] += (vv && (lb == l));
    }
#pragma unroll
    for (int o = 16; o >= 1; o >>= 1)
#pragma unroll
        for (int k = 0; k < 6; k++) c[k] += __shfl_xor_sync(0xffffffffu, c[k], o);
    if (lane == 0)
#pragma unroll
        for (int k = 0; k < 6; k++) cbuf[w][k] = c[k];
    __syncthreads();
    for (int sidx = tid; sidx < 512; sidx += 256) {
        int l = sidx >> 7, d = sidx & 127;
        g_P[b * 512 + l * 128 + d] = Pp[l * 128 + d] + Pp[512 + l * 128 + d] +
                                     Pp[1024 + l * 128 + d] + Pp[1536 + l * 128 + d];
    }
    if (tid < 6) {
        int t = 0;
        for (int ww = 0; ww < 8; ww++) t += cbuf[ww][tid];
        if (tid == 0) g_counts[b].x = t;
        else if (tid == 1) g_counts[b].y = t;
        else g_cnt4[b * 4 + (tid - 2)] = t;
    }
}

// ---------------------------------------------------------------------------
// Kernel 2: sim-HMMA + exp-row-sum only (mask-free). Writes g_se per anchor.
// M=64 rows/CTA (512 CTAs). Diagonal excluded in-kernel (1 of 8 tiles).
// ---------------------------------------------------------------------------
#define SM2_RED 0
#define SM2_A   1024
#define SM2_B   (1024 + 16384)
#define SIM_SMEM (1024 + 16384 + 32768)

__global__ __launch_bounds__(256, 3)
void kern_sim() {
    extern __shared__ char sm[];
    const unsigned sb = smem_to_u32(sm);
    const int tid = threadIdx.x, lane = tid & 31, wid = tid >> 5;
    const int wm = wid & 1, wn = wid >> 1;
    const int m0 = wm * 32, n0 = wn * 32;
    const int b = blockIdx.x >> 4, it = blockIdx.x & 15;
    const int i0 = it * 64;
    const __half* eb = g_emb + (size_t)b * LL * PP;
    const int sh = (lane & 3) * 2;

#pragma unroll
    for (int i = 0; i < 4; i++) {
        int u = i * 256 + tid;
        int row = u >> 4, k8 = u & 15;
        unsigned off = (unsigned)((k8 >> 3) * 8192) +
                       sw128((unsigned)(row * 128 + (k8 & 7) * 16));
        CP16(sb + SM2_A + off, eb + (size_t)(i0 + row) * PP + k8 * 8);
    }
#pragma unroll
    for (int i = 0; i < 8; i++) {
        int u = i * 256 + tid;
        int row = u >> 4, k8 = u & 15;
        unsigned off = (unsigned)((k8 >> 3) * 16384) +
                       sw128((unsigned)(row * 128 + (k8 & 7) * 16));
        CP16(sb + SM2_B + off, eb + (size_t)row * PP + k8 * 8);
    }
    CP_COMMIT();

    float se_[4] = {0.f, 0.f, 0.f, 0.f};

#pragma unroll 1
    for (int jt = 0; jt < 8; jt++) {
        CP_WAIT0();
        __syncthreads();

        float acc[2][4][4];
#pragma unroll
        for (int mt = 0; mt < 2; mt++)
#pragma unroll
            for (int nt = 0; nt < 4; nt++)
#pragma unroll
                for (int e = 0; e < 4; e++) acc[mt][nt][e] = 0.f;

#pragma unroll
        for (int kk = 0; kk < 8; kk++) {
            const unsigned chA = (unsigned)((kk >> 2) * 8192);
            const unsigned chB = (unsigned)((kk >> 2) * 16384);
            const unsigned kk2 = (kk & 3) * 32;
            unsigned ah[2][4], bh[4][2];
#pragma unroll
            for (int mt = 0; mt < 2; mt++) {
                unsigned r = m0 + mt * 16 + (lane & 15);
                unsigned off = chA + sw128(r * 128 + kk2 + ((lane >> 4) << 4));
                LDSM4(ah[mt][0], ah[mt][1], ah[mt][2], ah[mt][3], sb + SM2_A + off);
            }
#pragma unroll
            for (int p = 0; p < 2; p++) {
                unsigned q = lane >> 3;
                unsigned nr = n0 + p * 16 + ((q >> 1) << 3) + (lane & 7);
                unsigned off = chB + sw128(nr * 128 + kk2 + ((q & 1) << 4));
                unsigned t0, t1, t2, t3;
                LDSM4(t0, t1, t2, t3, sb + SM2_B + off);
                bh[2 * p][0] = t0; bh[2 * p][1] = t1;
                bh[2 * p + 1][0] = t2; bh[2 * p + 1][1] = t3;
            }
#pragma unroll
            for (int mt = 0; mt < 2; mt++)
#pragma unroll
                for (int nt = 0; nt < 4; nt++)
                    MMA(acc[mt][nt], ah[mt], bh[nt]);
        }

        // epilogue: se += ex2(C1*(s-1)); skip diagonal in the diagonal tile
        const int dt = (jt == (it >> 1));
#pragma unroll
        for (int r2 = 0; r2 < 4; r2++) {
            int mt = r2 >> 1, s = r2 & 1;
            float se = se_[r2];
            if (dt) {
                int rowg = wm * 32 + mt * 16 + (lane >> 2) + s * 8;
                int cdr = (it & 1) * 64 + rowg;
#pragma unroll
                for (int nt = 0; nt < 4; nt++)
#pragma unroll
                    for (int cc = 0; cc < 2; cc++) {
                        int cloc = n0 + nt * 8 + sh + cc;
                        float e = ex2f(fmaf(acc[mt][nt][s * 2 + cc], C1F, -C1F));
                        se += (cloc == cdr) ? 0.f : e;
                    }
            } else {
#pragma unroll
                for (int nt = 0; nt < 4; nt++)
#pragma unroll
                    for (int cc = 0; cc < 2; cc++)
                        se += ex2f(fmaf(acc[mt][nt][s * 2 + cc], C1F, -C1F));
            }
            se_[r2] = se;
        }
        __syncthreads();
        if (jt < 7) {
            const int j0n = (jt + 1) * 128;
#pragma unroll
            for (int i = 0; i < 8; i++) {
                int u = i * 256 + tid;
                int row = u >> 4, k8 = u & 15;
                unsigned off = (unsigned)((k8 >> 3) * 16384) +
                               sw128((unsigned)(row * 128 + (k8 & 7) * 16));
                CP16(sb + SM2_B + off, eb + (size_t)(j0n + row) * PP + k8 * 8);
            }
            CP_COMMIT();
        }
    }

    // merge se: 4 lanes per row, then 4 n-warp-groups via smem
#pragma unroll
    for (int o = 1; o <= 2; o <<= 1)
#pragma unroll
        for (int r2 = 0; r2 < 4; r2++)
            se_[r2] += __shfl_xor_sync(0xffffffffu, se_[r2], o);
    float* red = (float*)(sm + SM2_RED);
    if ((lane & 3) == 0) {
#pragma unroll
        for (int r2 = 0; r2 < 4; r2++) {
            int rowg = wm * 32 + (r2 >> 1) * 16 + (lane >> 2) + (r2 & 1) * 8;
            red[wn * 64 + rowg] = se_[r2];
        }
    }
    __syncthreads();
    if (wn == 0 && (lane & 3) == 0) {
#pragma unroll
        for (int r2 = 0; r2 < 4; r2++) {
            int rowg = wm * 32 + (r2 >> 1) * 16 + (lane >> 2) + (r2 & 1) * 8;
            g_se[(size_t)b * LL + i0 + rowg] =
                red[rowg] + red[64 + rowg] + red[128 + rowg] + red[192 + rowg];
        }
    }
}

// ---------------------------------------------------------------------------
// Kernel POS: per-anchor loss via P_l dots; per-batch loss_seq
// ---------------------------------------------------------------------------
__global__ __launch_bounds__(1024)
void kern_pos(const int* __restrict__ amask, const int* __restrict__ labels) {
    __shared__ float Ps[512];
    __shared__ float als[32];
    const int b = blockIdx.x, tid = threadIdx.x, lane = tid & 31, w = tid >> 5;
    if (tid < 512) Ps[tid] = g_P[b * 512 + tid];
    __syncthreads();
    const int2 cnts = g_counts[b];
    const float corrE = ex2f(-C1F);
    const float ninv = (float)(LL - cnts.y);
    float alsum = 0.f;
#pragma unroll 1
    for (int iter = 0; iter < 32; iter++) {
        int a = iter * 32 + w;
        uint2 hh = *(const uint2*)(g_emb + ((size_t)b * LL + a) * PP + lane * 4);
        float2 f0 = __half22float2(*(__half2*)&hh.x);
        float2 f1 = __half22float2(*(__half2*)&hh.y);
        int lb = labels[b * LL + a];
        int vv = (amask[b * LL + a] != 0) && (lb != -100);
        int l4 = vv ? lb : 0;
        float4 pv = *(const float4*)(Ps + l4 * 128 + lane * 4);
        float dp = f0.x * pv.x + f0.y * pv.y + f1.x * pv.z + f1.y * pv.w;
        float sf = f0.x * f0.x + f0.y * f0.y + f1.x * f1.x + f1.y * f1.y;
#pragma unroll
        for (int o = 16; o >= 1; o >>= 1) {
            dp += __shfl_xor_sync(0xffffffffu, dp, o);
            sf += __shfl_xor_sync(0xffffffffu, sf, o);
        }
        if (lane == 0) {
            int np = vv ? (g_cnt4[b * 4 + l4] - 1) : 0;
            if (np > 0) {
                float sii = INVT * sf;
                float sp = INVT * dp - sii;
                float se = g_se[b * LL + a] - ninv * corrE;
                alsum += (sp - (float)np * (INVT + __logf(se + 1e-12f))) / (float)np;
            }
        }
    }
    if (lane == 0) als[w] = alsum;
    __syncthreads();
    if (tid == 0) {
        float ps = 0.f;
        for (int i = 0; i < 32; i++) ps += als[i];
        int ok = (cnts.x >= 2);
        float nv = (float)(cnts.y >= 1 ? cnts.y : 1);
        g_loss[b] = ok ? (-ps / nv) : 0.f;
        g_ok[b] = ok;
    }
}

// ---------------------------------------------------------------------------
// Kernel FINAL
// ---------------------------------------------------------------------------
__global__ void kern_final(float* __restrict__ out) {
    const int lane = threadIdx.x;
    float s = g_loss[lane];
    int ns = g_ok[lane];
#pragma unroll
    for (int o = 16; o >= 1; o >>= 1) {
        s += __shfl_xor_sync(0xffffffffu, s, o);
        ns += __shfl_xor_sync(0xffffffffu, ns, o);
    }
    if (lane == 0) out[0] = s / (float)(ns > 0 ? ns : 1);
}

// ---------------------------------------------------------------------------
extern "C" void kernel_launch(void* const* d_in, const int* in_sizes, int n_in,
                              void* d_out, int out_size) {
    const float* hid = (const float*)d_in[0];
    const float* W = (const float*)d_in[1];
    const float* bias = (const float*)d_in[2];
    const int* amask = (const int*)d_in[3];
    const int* labels = (const int*)d_in[4];
    float* out = (float*)d_out;

    cudaFuncSetAttribute(kern_proj, cudaFuncAttributeMaxDynamicSharedMemorySize, PROJ_SMEM);
    cudaFuncSetAttribute(kern_sim, cudaFuncAttributeMaxDynamicSharedMemorySize, SIM_SMEM);

    kern_wt<<<(HH * PP + 255) / 256, 256>>>(W);                    // 0
    kern_proj<<<NROWS / 128, 256, PROJ_SMEM>>>(hid, bias, amask, labels); // 1
    kern_pl<<<BB, 256>>>(amask, labels);                           // 2
    kern_sim<<<BB * 16, 256, SIM_SMEM>>>();                        // 3 (ncu slot)
    kern_pos<<<BB, 1024>>>(amask, labels);                         // 4
    kern_final<<<1, 32>>>(out);                                    // 5
}

// round 9
// speedup vs baseline: 1.6393x; 1.6393x over previous
#include <cuda_runtime.h>
#include <cuda_fp16.h>

#define BB 32
#define LL 1024
#define HH 1280
#define PP 128
#define NROWS (BB * LL)

// ---------------------------------------------------------------------------
// Helpers
// ---------------------------------------------------------------------------
__device__ __forceinline__ unsigned smem_to_u32(const void* p) {
    unsigned a;
    asm("{ .reg .u64 t; cvta.to.shared.u64 t, %1; cvt.u32.u64 %0, t; }" : "=r"(a) : "l"(p));
    return a;
}
static __device__ __forceinline__ unsigned sw128(unsigned off) {
    return off ^ ((off >> 3) & 0x70);
}
__device__ __forceinline__ unsigned f16pack(float lo, float hi) {
    unsigned r;
    asm("cvt.rn.f16x2.f32 %0, %1, %2;" : "=r"(r) : "f"(hi), "f"(lo));
    return r;
}

#define LDSM4(r0, r1, r2, r3, addr)                                          \
    asm volatile("ldmatrix.sync.aligned.m8n8.x4.shared.b16 {%0,%1,%2,%3}, [%4];" \
                 : "=r"(r0), "=r"(r1), "=r"(r2), "=r"(r3) : "r"(addr))

#define MMA(d, a, b)                                                         \
    asm volatile("mma.sync.aligned.m16n8k16.row.col.f32.f16.f16.f32 "        \
                 "{%0,%1,%2,%3},{%4,%5,%6,%7},{%8,%9},{%0,%1,%2,%3};"        \
                 : "+f"((d)[0]), "+f"((d)[1]), "+f"((d)[2]), "+f"((d)[3])    \
                 : "r"((a)[0]), "r"((a)[1]), "r"((a)[2]), "r"((a)[3]),       \
                   "r"((b)[0]), "r"((b)[1]))

#define CP16(dst, src) \
    asm volatile("cp.async.cg.shared.global [%0], [%1], 16;" :: "r"(dst), "l"(src))
#define CP_COMMIT() asm volatile("cp.async.commit_group;" ::: "memory")
#define CP_WAIT1()  asm volatile("cp.async.wait_group 1;" ::: "memory")
#define CP_WAIT0()  asm volatile("cp.async.wait_group 0;" ::: "memory")

// ---------------------------------------------------------------------------
// Device scratch
// ---------------------------------------------------------------------------
__device__ __align__(16) __half g_emb[NROWS * PP];
__device__ __align__(16) __half g_wt[PP * HH];   // [n][k] K-major
__device__ float g_partial[BB * 16];
__device__ int2 g_counts[BB];

// ---------------------------------------------------------------------------
// Kernel 0: W -> fp16, transposed to [n][k]
// ---------------------------------------------------------------------------
__global__ void kern_wt(const float* __restrict__ W) {
    int i = blockIdx.x * 256 + threadIdx.x;
    if (i >= HH * PP) return;
    int k = i / PP, n = i % PP;
    g_wt[n * HH + k] = __float2half_rn(W[i]);
}

// empty pad kernel (aligns the ncu capture slot onto kern_sim)
__global__ void kern_nop() {}

// ---------------------------------------------------------------------------
// Kernel 1: proj + L2-normalize (single-term fp16 HMMA)
// ---------------------------------------------------------------------------
#define P_A  4096
#define P_B0 20480
#define PROJ_SMEM (20480 + 2 * 16384)

__global__ __launch_bounds__(256, 2)
void kern_proj(const float* __restrict__ hid, const float* __restrict__ bias) {
    extern __shared__ char sm[];
    const unsigned sb = smem_to_u32(sm);
    const int tid = threadIdx.x, lane = tid & 31, wid = tid >> 5;
    const int wm = wid & 3, wn = wid >> 2;
    const int m0 = wm * 32, n0 = wn * 64;
    const int row0 = blockIdx.x * 128;
    float* bias_s = (float*)sm;
    float* ssbuf = (float*)(sm + 512);

    if (tid < 128) bias_s[tid] = bias[tid];

    float acc[2][8][4];
#pragma unroll
    for (int mt = 0; mt < 2; mt++)
#pragma unroll
        for (int nt = 0; nt < 8; nt++)
#pragma unroll
            for (int e = 0; e < 4; e++) acc[mt][nt][e] = 0.f;

#pragma unroll
    for (int i = 0; i < 4; i++) {
        int u = i * 256 + tid;
        int n = u >> 3, k8 = u & 7;
        unsigned off = sw128((unsigned)(n * 128 + k8 * 16));
        CP16(sb + P_B0 + off, g_wt + (size_t)n * HH + k8 * 8);
    }
    CP_COMMIT();

    uint4 ra[4];
#pragma unroll
    for (int q = 0; q < 4; q++) {
        int u = q * 256 + tid;
        int row = u >> 3, k8 = u & 7;
        const float* s = hid + (size_t)(row0 + row) * HH + k8 * 8;
        float4 v0 = *(const float4*)s;
        float4 v1 = *(const float4*)(s + 4);
        ra[q] = make_uint4(f16pack(v0.x, v0.y), f16pack(v0.z, v0.w),
                           f16pack(v1.x, v1.y), f16pack(v1.z, v1.w));
    }

#pragma unroll 1
    for (int c = 0; c < 20; c++) {
        const int buf = c & 1;
        __syncthreads();
        if (c < 19) {
            const int k0n = (c + 1) * 64;
            const unsigned bdst = sb + P_B0 + (buf ^ 1) * 16384;
#pragma unroll
            for (int i = 0; i < 4; i++) {
                int u = i * 256 + tid;
                int n = u >> 3, k8 = u & 7;
                unsigned off = sw128((unsigned)(n * 128 + k8 * 16));
                CP16(bdst + off, g_wt + (size_t)n * HH + k0n + k8 * 8);
            }
            CP_COMMIT();
        }
#pragma unroll
        for (int q = 0; q < 4; q++) {
            int u = q * 256 + tid;
            int row = u >> 3, k8 = u & 7;
            unsigned off = sw128((unsigned)(row * 128 + k8 * 16));
            *(uint4*)(sm + P_A + off) = ra[q];
        }
        if (c < 19) {
            const int k0n = (c + 1) * 64;
#pragma unroll
            for (int q = 0; q < 4; q++) {
                int u = q * 256 + tid;
                int row = u >> 3, k8 = u & 7;
                const float* s = hid + (size_t)(row0 + row) * HH + k0n + k8 * 8;
                float4 v0 = *(const float4*)s;
                float4 v1 = *(const float4*)(s + 4);
                ra[q] = make_uint4(f16pack(v0.x, v0.y), f16pack(v0.z, v0.w),
                                   f16pack(v1.x, v1.y), f16pack(v1.z, v1.w));
            }
        }
        if (c < 19) CP_WAIT1(); else CP_WAIT0();
        __syncthreads();

        const unsigned b_base = sb + P_B0 + buf * 16384;
#pragma unroll
        for (int kk = 0; kk < 4; kk++) {
            unsigned ah[2][4], bh[8][2];
#pragma unroll
            for (int mt = 0; mt < 2; mt++) {
                unsigned r = m0 + mt * 16 + (lane & 15);
                unsigned off = sw128(r * 128 + kk * 32 + ((lane >> 4) << 4));
                LDSM4(ah[mt][0], ah[mt][1], ah[mt][2], ah[mt][3], sb + P_A + off);
            }
#pragma unroll
            for (int p = 0; p < 4; p++) {
                unsigned q = lane >> 3;
                unsigned nr = n0 + p * 16 + ((q >> 1) << 3) + (lane & 7);
                unsigned off = sw128(nr * 128 + kk * 32 + ((q & 1) << 4));
                unsigned t0, t1, t2, t3;
                LDSM4(t0, t1, t2, t3, b_base + off);
                bh[2 * p][0] = t0; bh[2 * p][1] = t1;
                bh[2 * p + 1][0] = t2; bh[2 * p + 1][1] = t3;
            }
#pragma unroll
            for (int mt = 0; mt < 2; mt++)
#pragma unroll
                for (int nt = 0; nt < 8; nt++)
                    MMA(acc[mt][nt], ah[mt], bh[nt]);
        }
    }

    // epilogue: bias, L2 norm, store fp16 emb
    float ss[4] = {0.f, 0.f, 0.f, 0.f};
#pragma unroll
    for (int mt = 0; mt < 2; mt++)
#pragma unroll
        for (int nt = 0; nt < 8; nt++)
#pragma unroll
            for (int e = 0; e < 4; e++) {
                int s = e >> 1;
                int col = n0 + nt * 8 + (lane & 3) * 2 + (e & 1);
                float v = acc[mt][nt][e] + bias_s[col];
                acc[mt][nt][e] = v;
                ss[mt * 2 + s] += v * v;
            }
#pragma unroll
    for (int r2 = 0; r2 < 4; r2++) {
        ss[r2] += __shfl_xor_sync(0xffffffffu, ss[r2], 1);
        ss[r2] += __shfl_xor_sync(0xffffffffu, ss[r2], 2);
    }
    if ((lane & 3) == 0) {
#pragma unroll
        for (int r2 = 0; r2 < 4; r2++) {
            int rowg = wm * 32 + (r2 >> 1) * 16 + (lane >> 2) + (r2 & 1) * 8;
            ssbuf[wn * 128 + rowg] = ss[r2];
        }
    }
    __syncthreads();
#pragma unroll
    for (int r2 = 0; r2 < 4; r2++) {
        int mt = r2 >> 1, s = r2 & 1;
        int rowg = wm * 32 + mt * 16 + (lane >> 2) + s * 8;
        float tot = ssbuf[rowg] + ssbuf[128 + rowg];
        float inv = rsqrtf(tot);
        inv = inv * (1.5f - 0.5f * tot * inv * inv);
        __half* oh = g_emb + (size_t)(row0 + rowg) * PP;
#pragma unroll
        for (int nt = 0; nt < 8; nt++) {
            int col = n0 + nt * 8 + (lane & 3) * 2;
            *(unsigned*)(oh + col) =
                f16pack(acc[mt][nt][s * 2] * inv, acc[mt][nt][s * 2 + 1] * inv);
        }
    }
}

// ---------------------------------------------------------------------------
// Kernel 2: fused sim-HMMA + contrastive stats (single-term fp16).
// M=64 rows/CTA (512 CTAs), fixed-shift softmax (m = 1/T), ballot bitmasks,
// single-buffered B, OCCUPANCY 4 (single wave: 592 slots >= 512 CTAs).
// ---------------------------------------------------------------------------
#define SM2_WPART 0
#define SM2_MASK  64
#define SM2_CNT   160
#define SM2_RED   256
#define SM2_A     5120
#define SM2_B     21504
#define SIM_SMEM  54272

__global__ __launch_bounds__(256, 4)
void kern_sim(const int* __restrict__ amask, const int* __restrict__ labels) {
    extern __shared__ char sm[];
    const unsigned sb = smem_to_u32(sm);
    const int tid = threadIdx.x, lane = tid & 31, wid = tid >> 5;
    const int wm = wid & 1, wn = wid >> 1;
    const int m0 = wm * 32, n0 = wn * 32;
    const int b = blockIdx.x >> 4, it = blockIdx.x & 15;
    const int i0 = it * 64;
    const __half* eb = g_emb + (size_t)b * LL * PP;
    float* wpart = (float*)(sm + SM2_WPART);
    unsigned* valm = (unsigned*)(sm + SM2_MASK);
    unsigned* posm = valm + 4;
    int* cnt = (int*)(sm + SM2_CNT);

    // A tile (64 rows): 4 CP16/thread
#pragma unroll
    for (int i = 0; i < 4; i++) {
        int u = i * 256 + tid;
        int row = u >> 4, k8 = u & 15;
        unsigned off = (unsigned)((k8 >> 3) * 8192) +
                       sw128((unsigned)(row * 128 + (k8 & 7) * 16));
        CP16(sb + SM2_A + off, eb + (size_t)(i0 + row) * PP + k8 * 8);
    }
    // B tile 0 (128 rows): 8 CP16/thread
#pragma unroll
    for (int i = 0; i < 8; i++) {
        int u = i * 256 + tid;
        int row = u >> 4, k8 = u & 15;
        unsigned off = (unsigned)((k8 >> 3) * 16384) +
                       sw128((unsigned)(row * 128 + (k8 & 7) * 16));
        CP16(sb + SM2_B + off, eb + (size_t)row * PP + k8 * 8);
    }
    CP_COMMIT();

    // labi sentinel: -1 means invalid anchor
    int labi_[4], np_[4];
    float se_[4], sp_[4];
#pragma unroll
    for (int r2 = 0; r2 < 4; r2++) {
        int rowg = wm * 32 + (r2 >> 1) * 16 + (lane >> 2) + (r2 & 1) * 8;
        int gi = i0 + rowg;
        int lb = labels[b * LL + gi];
        labi_[r2] = ((amask[b * LL + gi] != 0) && (lb != -100)) ? lb : -1;
        se_[r2] = 0.f; sp_[r2] = 0.f; np_[r2] = 0;
    }
    const float invT = 1.0f / 0.07f;

#pragma unroll 1
    for (int jt = 0; jt < 8; jt++) {
        const int j0 = jt * 128;
        if (tid < 128) {
            int mm = amask[b * LL + j0 + tid];
            int lb = labels[b * LL + j0 + tid];
            int vv = (mm != 0) && (lb != -100);
            unsigned vmb = __ballot_sync(0xffffffffu, vv);
            if (lane == 0) valm[wid] = vmb;
#pragma unroll
            for (int l = 0; l < 4; l++) {
                unsigned pb = __ballot_sync(0xffffffffu, vv && (lb == l));
                if (lane == 0) posm[l * 4 + wid] = pb;
            }
        }
        CP_WAIT0();
        __syncthreads();

        float acc[2][4][4];
#pragma unroll
        for (int mt = 0; mt < 2; mt++)
#pragma unroll
            for (int nt = 0; nt < 4; nt++)
#pragma unroll
                for (int e = 0; e < 4; e++) acc[mt][nt][e] = 0.f;

#pragma unroll
        for (int kk = 0; kk < 8; kk++) {
            const unsigned chA = (unsigned)((kk >> 2) * 8192);
            const unsigned chB = (unsigned)((kk >> 2) * 16384);
            const unsigned kk2 = (kk & 3) * 32;
            unsigned ah[2][4], bh[4][2];
#pragma unroll
            for (int mt = 0; mt < 2; mt++) {
                unsigned r = m0 + mt * 16 + (lane & 15);
                unsigned off = chA + sw128(r * 128 + kk2 + ((lane >> 4) << 4));
                LDSM4(ah[mt][0], ah[mt][1], ah[mt][2], ah[mt][3], sb + SM2_A + off);
            }
#pragma unroll
            for (int p = 0; p < 2; p++) {
                unsigned q = lane >> 3;
                unsigned nr = n0 + p * 16 + ((q >> 1) << 3) + (lane & 7);
                unsigned off = chB + sw128(nr * 128 + kk2 + ((q & 1) << 4));
                unsigned t0, t1, t2, t3;
                LDSM4(t0, t1, t2, t3, sb + SM2_B + off);
                bh[2 * p][0] = t0; bh[2 * p][1] = t1;
                bh[2 * p + 1][0] = t2; bh[2 * p + 1][1] = t3;
            }
#pragma unroll
            for (int mt = 0; mt < 2; mt++)
#pragma unroll
                for (int nt = 0; nt < 4; nt++)
                    MMA(acc[mt][nt], ah[mt], bh[nt]);
        }

        // fixed-shift epilogue (m = invT), bitmask-gated
        const unsigned vmw = valm[wn];
        const int dt = (jt == (it >> 1));
        const int sh = (lane & 3) * 2;
#pragma unroll
        for (int r2 = 0; r2 < 4; r2++) {
            int mt = r2 >> 1, s = r2 & 1;
            int rowg = wm * 32 + mt * 16 + (lane >> 2) + s * 8;
            unsigned vmr = vmw;
            if (dt) {
                int cd = (it & 1) * 64 + rowg;
                if ((cd >> 5) == wn) vmr &= ~(1u << (cd & 31));
            }
            unsigned pmr = (labi_[r2] >= 0) ? (posm[labi_[r2] * 4 + wn] & vmr) : 0u;
            float se = se_[r2], sp = sp_[r2];
            int np = np_[r2];
#pragma unroll
            for (int nt = 0; nt < 4; nt++)
#pragma unroll
                for (int cc = 0; cc < 2; cc++) {
                    int bp = nt * 8 + sh + cc;
                    float v = acc[mt][nt][s * 2 + cc] * invT;
                    float e = __expf(v - invT);
                    if ((vmr >> bp) & 1) se += e;
                    if ((pmr >> bp) & 1) { sp += v; np++; }
                }
            se_[r2] = se; sp_[r2] = sp; np_[r2] = np;
        }
        __syncthreads();
        if (jt < 7) {
            const int j0n = j0 + 128;
#pragma unroll
            for (int i = 0; i < 8; i++) {
                int u = i * 256 + tid;
                int row = u >> 4, k8 = u & 15;
                unsigned off = (unsigned)((k8 >> 3) * 16384) +
                               sw128((unsigned)(row * 128 + (k8 & 7) * 16));
                CP16(sb + SM2_B + off, eb + (size_t)(j0n + row) * PP + k8 * 8);
            }
            CP_COMMIT();
        }
    }

    // per-batch counts: recomputed AFTER mainloop; ALL 8 warps contribute
    if (it == 0) {
        int cm = 0, cv = 0;
#pragma unroll
        for (int q = 0; q < 4; q++) {
            int row = q * 256 + tid;
            int mm = amask[b * LL + row];
            int lb = labels[b * LL + row];
            cm += (mm != 0);
            cv += (mm != 0) && (lb != -100);
        }
#pragma unroll
        for (int o = 16; o >= 1; o >>= 1) {
            cm += __shfl_xor_sync(0xffffffffu, cm, o);
            cv += __shfl_xor_sync(0xffffffffu, cv, o);
        }
        if (lane == 0) { cnt[wid * 2] = cm; cnt[wid * 2 + 1] = cv; }
    }

    // merge stats across the 4 lanes sharing each row (pure adds)
#pragma unroll
    for (int o = 1; o <= 2; o <<= 1)
#pragma unroll
        for (int r2 = 0; r2 < 4; r2++) {
            se_[r2] += __shfl_xor_sync(0xffffffffu, se_[r2], o);
            sp_[r2] += __shfl_xor_sync(0xffffffffu, sp_[r2], o);
            np_[r2] += __shfl_xor_sync(0xffffffffu, np_[r2], o);
        }
    if ((lane & 3) == 0) {
#pragma unroll
        for (int r2 = 0; r2 < 4; r2++) {
            int rowg = wm * 32 + (r2 >> 1) * 16 + (lane >> 2) + (r2 & 1) * 8;
            *(float4*)(sm + SM2_RED + (wn * 64 + rowg) * 16) =
                make_float4(se_[r2], sp_[r2], (float)np_[r2], 0.f);
        }
    }
    __syncthreads();
    float alsum = 0.f;
    if (wn == 0 && (lane & 3) == 0) {
#pragma unroll
        for (int r2 = 0; r2 < 4; r2++) {
            int rowg = wm * 32 + (r2 >> 1) * 16 + (lane >> 2) + (r2 & 1) * 8;
            float se = 0.f, sp = 0.f, np = 0.f;
#pragma unroll
            for (int w = 0; w < 4; w++) {
                float4 q = *(const float4*)(sm + SM2_RED + (w * 64 + rowg) * 16);
                se += q.x; sp += q.y; np += q.z;
            }
            alsum += (sp - np * (invT + __logf(se + 1e-12f))) / (np + 1e-12f);
        }
    }
    if (wn == 0) {
#pragma unroll
        for (int o = 16; o >= 1; o >>= 1)
            alsum += __shfl_xor_sync(0xffffffffu, alsum, o);
        if (lane == 0) wpart[wid] = alsum;
    }
    __syncthreads();
    if (tid == 0) {
        g_partial[blockIdx.x] = wpart[0] + wpart[1];
        if (it == 0) {
            // FIX (R8 bug): sum ALL 8 warps' partial counts (cnt[0..15])
            int tm = 0, tv = 0;
#pragma unroll
            for (int w = 0; w < 8; w++) { tm += cnt[w * 2]; tv += cnt[w * 2 + 1]; }
            g_counts[b] = make_int2(tm, tv);
        }
    }
}

// ---------------------------------------------------------------------------
// Kernel 3: tiny deterministic final reduction (counts precomputed)
// ---------------------------------------------------------------------------
__global__ void kern_final(float* __restrict__ out) {
    __shared__ float lossb[32];
    __shared__ int okb[32];
    const int w = threadIdx.x >> 5;
    const int lane = threadIdx.x & 31;
    float ps = (lane < 16) ? g_partial[w * 16 + lane] : 0.f;
#pragma unroll
    for (int o = 8; o >= 1; o >>= 1) ps += __shfl_xor_sync(0xffffffffu, ps, o);
    if (lane == 0) {
        int2 c = g_counts[w];
        int ok = (c.x >= 2);
        float nv = (float)(c.y >= 1 ? c.y : 1);
        lossb[w] = ok ? (-ps / nv) : 0.f;
        okb[w] = ok;
    }
    __syncthreads();
    if (threadIdx.x == 0) {
        float s = 0.f;
        int ns = 0;
        for (int bq = 0; bq < 32; bq++) { s += lossb[bq]; ns += okb[bq]; }
        out[0] = s / (float)(ns > 0 ? ns : 1);
    }
}

// ---------------------------------------------------------------------------
extern "C" void kernel_launch(void* const* d_in, const int* in_sizes, int n_in,
                              void* d_out, int out_size) {
    const float* hid = (const float*)d_in[0];
    const float* W = (const float*)d_in[1];
    const float* bias = (const float*)d_in[2];
    const int* amask = (const int*)d_in[3];
    const int* labels = (const int*)d_in[4];
    float* out = (float*)d_out;

    cudaFuncSetAttribute(kern_proj, cudaFuncAttributeMaxDynamicSharedMemorySize, PROJ_SMEM);
    cudaFuncSetAttribute(kern_sim, cudaFuncAttributeMaxDynamicSharedMemorySize, SIM_SMEM);

    // 6-launch period; ncu capture slot (#3) lands on kern_sim
    kern_wt<<<(HH * PP + 255) / 256, 256>>>(W);                    // 0
    kern_proj<<<NROWS / 128, 256, PROJ_SMEM>>>(hid, bias);         // 1
    kern_nop<<<1, 32>>>();                                         // 2
    kern_sim<<<BB * 16, 256, SIM_SMEM>>>(amask, labels);           // 3 (ncu)
    kern_final<<<1, 1024>>>(out);                                  // 4
    kern_nop<<<1, 32>>>();                                         // 5
}